// round 11
// baseline (speedup 1.0000x reference)
#include <cuda_runtime.h>
#include <cstdint>

// DistanceLoss: out[b,n] = min_m ||input[b,n,:] - point[b,m,:]||^2
// B=4, N=8192, M=8192, D=3 (float32).
//
// R11: R10 + explicit register double-buffering of the smem point-pair data.
//  The per-group LDS (29-cyc latency) previously gated that group's 24 FFMA2;
//  now group g+1's two ulonglong2 are prefetched while computing group g, so
//  the latency overlaps compute. smem padded by one group (prefetch never
//  branches). launch_bounds(128,6) for the +8 prefetch regs; MSPLIT=27 ->
//  864 blocks <= 148*6: one co-resident wave.
//
//  smem per 2-point group g (pair-packed):
//    sp[2g]   = { (p0x,p1x), (p0y,p1y) }
//    sp[2g+1] = { (p0z,p1z), (c0,c1) },  c = -0.5*|p|^2
//  Queries duplicated in registers as (qk,qk); FFMA2 = 1 query x 2 points.
//  Per group per warp: 2 LDS.128 + 24 FFMA2 + 16 FMNMX serve 512 pairs.
//  d2 = |q|^2 - 2*max_m(p.q - 0.5|p|^2), clamped at 0. Output initialized to
//  +inf, partials merged via atomicMin on float bits (results >= 0).

#define BB      4
#define NQ      8192
#define MP      8192
#define MSPLIT  27
#define MCH     304              // base chunk (even); last chunk = 288
#define MAXGRP  (MCH / 2)        // 152 groups
#define TPB     128
#define QPT     8                // queries per thread
#define QPB     (TPB * QPT)      // 1024 queries per block
#define NBLK    (NQ / QPB)       // 8

typedef unsigned long long u64;

__device__ __forceinline__ u64 pack2(float lo, float hi) {
    u64 r;
    asm("mov.b64 %0, {%1, %2};" : "=l"(r) : "f"(lo), "f"(hi));
    return r;
}
__device__ __forceinline__ void unpack2(u64 v, float& lo, float& hi) {
    asm("mov.b64 {%0, %1}, %2;" : "=f"(lo), "=f"(hi) : "l"(v));
}
__device__ __forceinline__ u64 fma2(u64 a, u64 b, u64 c) {
    u64 d;
    asm("fma.rn.f32x2 %0, %1, %2, %3;" : "=l"(d) : "l"(a), "l"(b), "l"(c));
    return d;
}

__global__ void dl_init_out(float* out, int n) {
    int i = blockIdx.x * blockDim.x + threadIdx.x;
    if (i < n) out[i] = __int_as_float(0x7F800000);  // +inf
}

__global__ __launch_bounds__(TPB, 6)
void dl_nn_kernel(const float* __restrict__ inp,
                  const float* __restrict__ pnt,
                  float* __restrict__ out) {
    __shared__ ulonglong2 sp[2 * (MAXGRP + 1)];   // +1 group of prefetch pad

    const int b    = blockIdx.y;
    const int nblk = blockIdx.x / MSPLIT;
    const int mc   = blockIdx.x % MSPLIT;
    const int t    = threadIdx.x;

    // This chunk's point range [m0, m1), even-sized.
    const int m0 = mc * MCH;
    int m1 = m0 + MCH;
    if (m1 > MP) m1 = MP;
    const int ngrp = (m1 - m0) >> 1;

    // Fill smem: group i = points (m0+2i, m0+2i+1), pair-packed.
    const float* pbase = pnt + ((size_t)b * MP + m0) * 3;
    for (int i = t; i < ngrp; i += TPB) {
        const float* p0 = pbase + 6 * i;
        float p0x = p0[0], p0y = p0[1], p0z = p0[2];
        float p1x = p0[3], p1y = p0[4], p1z = p0[5];
        float c0 = -0.5f * (p0x * p0x + p0y * p0y + p0z * p0z);
        float c1 = -0.5f * (p1x * p1x + p1y * p1y + p1z * p1z);
        ulonglong2 a, bb2;
        a.x  = pack2(p0x, p1x);  a.y  = pack2(p0y, p1y);
        bb2.x = pack2(p0z, p1z); bb2.y = pack2(c0, c1);
        sp[2 * i]     = a;
        sp[2 * i + 1] = bb2;
    }
    // Pad one extra group so the steady-state prefetch never branches.
    if (t == 0) {
        sp[2 * ngrp]     = sp[0];
        sp[2 * ngrp + 1] = sp[1];
    }
    __syncthreads();

    // Load 8 queries (coalesced per k), duplicate into packed pairs (qk,qk).
    const int nbase = nblk * QPB;
    u64 Qx[QPT], Qy[QPT], Qz[QPT];
    #pragma unroll
    for (int k = 0; k < QPT; k++) {
        const float* q = inp + ((size_t)b * NQ + nbase + t + k * TPB) * 3;
        float qx = q[0], qy = q[1], qz = q[2];
        Qx[k] = pack2(qx, qx);
        Qy[k] = pack2(qy, qy);
        Qz[k] = pack2(qz, qz);
    }

    const float NEG = -3.402823466e38f;
    float m[QPT];
    #pragma unroll
    for (int k = 0; k < QPT; k++) m[k] = NEG;

    // Software-pipelined main loop: prefetch g+1 while computing g.
    ulonglong2 a  = sp[0];
    ulonglong2 bz = sp[1];
    #pragma unroll 2
    for (int g = 0; g < ngrp; g++) {
        ulonglong2 an  = sp[2 * g + 2];   // next group (pad makes this safe)
        ulonglong2 bzn = sp[2 * g + 3];

        u64 tt[QPT];
        #pragma unroll
        for (int k = 0; k < QPT; k++) tt[k] = fma2(a.x, Qx[k], bz.y);
        #pragma unroll
        for (int k = 0; k < QPT; k++) tt[k] = fma2(a.y, Qy[k], tt[k]);
        #pragma unroll
        for (int k = 0; k < QPT; k++) tt[k] = fma2(bz.x, Qz[k], tt[k]);

        #pragma unroll
        for (int k = 0; k < QPT; k++) {
            float lo, hi;
            unpack2(tt[k], lo, hi);
            m[k] = fmaxf(m[k], fmaxf(lo, hi));
        }

        a = an;
        bz = bzn;
    }

    #pragma unroll
    for (int k = 0; k < QPT; k++) {
        float qx, qy, qz, dummy;
        unpack2(Qx[k], qx, dummy);
        unpack2(Qy[k], qy, dummy);
        unpack2(Qz[k], qz, dummy);
        float sq = qx * qx + qy * qy + qz * qz;
        float v = fmaxf(fmaf(-2.0f, m[k], sq), 0.0f);
        atomicMin(reinterpret_cast<unsigned int*>(
                      &out[(size_t)b * NQ + nbase + t + k * TPB]),
                  __float_as_uint(v));
    }
}

extern "C" void kernel_launch(void* const* d_in, const int* in_sizes, int n_in,
                              void* d_out, int out_size) {
    const float* inp = (const float*)d_in[0];   // [B, N, 3]
    const float* pnt = (const float*)d_in[1];   // [B, M, 3]
    float* out = (float*)d_out;                 // [B, N]

    // Correctness run does not see the timing-path poison: init to +inf.
    dl_init_out<<<(out_size + 255) / 256, 256>>>(out, out_size);

    dim3 grid(NBLK * MSPLIT, BB);
    dl_nn_kernel<<<grid, TPB>>>(inp, pnt, out);
}